// round 13
// baseline (speedup 1.0000x reference)
#include <cuda_runtime.h>
#include <cuda_bf16.h>
#include <cstdint>

// ---------------------------------------------------------------------------
// TransformerV2: conv feature branch + patch-similarity top-5 attention.
// Shapes fixed: B=1, Cin=64, Cq=32, H=W=96, L=9216, D=32*9=288.
// R12: similarity factorized over x-shifts: G1 = kcol·qcolT with K=96 column
//      features, R = masked 3-term diagonal sum of G1 (1.5x fewer MACs,
//      3x smaller GEMM operands, 2x fewer ldsm). Exact fp32 rescore keeps
//      final top-5 identical. Convs reverted to measured R10 kernels.
// ---------------------------------------------------------------------------

#define Hh 96
#define Ww 96
#define HW 9216
#define CIN 64
#define CQ  32
#define DQ  288
#define LQ  9216
#define KD  96          // column-feature dim (3dy x 32ch)

typedef unsigned long long ull;

// -------------------------- scratch (static, no allocs) --------------------
__device__ float g_t1  [CIN * HW];
__device__ float g_feat[CIN * HW];
__device__ float g_q   [CQ  * HW];
__device__ float g_k   [CQ  * HW];
__device__ float g_Qn  [LQ * DQ];          // fp32 normalized patches (rescore)
__device__ float g_Kn  [LQ * DQ];
__device__ __nv_bfloat16 g_colq[LQ * KD];  // raw 96-dim column features
__device__ __nv_bfloat16 g_colk[LQ * KD];
__device__ float g_rnk [LQ];               // 1 / ||kpatch||
__device__ float g_rnq [LQ];               // (unused by sim; symmetry)
__device__ float g_xT  [HW * CIN];
__device__ float g_tv  [LQ * 5];
__device__ int   g_ti  [LQ * 5];

// ======================= PTX helpers (compute_103-safe) ====================
__device__ __forceinline__ uint32_t smem_u32(const void* p) {
    uint32_t a;
    asm("{ .reg .u64 t; cvta.to.shared.u64 t, %1; cvt.u32.u64 %0, t; }"
        : "=r"(a) : "l"(p));
    return a;
}
__device__ __forceinline__ void cp16(uint32_t dst, const void* src) {
    asm volatile("cp.async.cg.shared.global [%0], [%1], 16;"
                 :: "r"(dst), "l"(src) : "memory");
}
__device__ __forceinline__ void cp4(uint32_t dst, const void* src) {
    asm volatile("cp.async.ca.shared.global [%0], [%1], 4;"
                 :: "r"(dst), "l"(src) : "memory");
}
#define CP_COMMIT() asm volatile("cp.async.commit_group;" ::: "memory")
#define CP_WAIT0()  asm volatile("cp.async.wait_group 0;" ::: "memory")

__device__ __forceinline__ void ldsm4(uint32_t* r, uint32_t addr) {
    asm volatile("ldmatrix.sync.aligned.m8n8.x4.shared.b16 {%0,%1,%2,%3}, [%4];"
                 : "=r"(r[0]), "=r"(r[1]), "=r"(r[2]), "=r"(r[3]) : "r"(addr));
}
__device__ __forceinline__ void mma16816(float* d, const uint32_t* a,
                                         const uint32_t* b) {
    asm volatile(
        "mma.sync.aligned.m16n8k16.row.col.f32.bf16.bf16.f32 "
        "{%0,%1,%2,%3}, {%4,%5,%6,%7}, {%8,%9}, {%0,%1,%2,%3};"
        : "+f"(d[0]), "+f"(d[1]), "+f"(d[2]), "+f"(d[3])
        : "r"(a[0]), "r"(a[1]), "r"(a[2]), "r"(a[3]), "r"(b[0]), "r"(b[1]));
}

// ---------------------------------------------------------------------------
// 3x3 SAME conv (R10 version — measured; 4 outs/block, pipelined).
// ---------------------------------------------------------------------------
template<int RPT>
__global__ void __launch_bounds__(256) conv3x3_t(
    const float* __restrict__ in,
    const float* __restrict__ wgt,
    const float* __restrict__ bias,
    float* __restrict__ out,
    int doRelu)
{
    constexpr int TH = 8 * RPT;
    constexpr int TL = (TH + 2) * 34;
    constexpr int NP = (TL + 255) / 256;

    __shared__ float tin[2][TH + 2][36];
    __shared__ float wsm[64][36];

    const int tx = threadIdx.x;
    const int ty = threadIdx.y;
    const int tid = ty * 32 + tx;
    const int x0 = blockIdx.x * 32;
    const int y0 = blockIdx.y * TH;
    const int og = blockIdx.z * 4;

    for (int i = tid; i < 4 * 64 * 9; i += 256) {
        int o = i / 576, rem = i - o * 576, ci = rem / 9, k = rem - ci * 9;
        wsm[ci][o * 9 + k] = wgt[((og + o) * 64 + ci) * 9 + k];
    }

    float pf[NP];
#pragma unroll
    for (int j = 0; j < NP; j++) {
        int i = tid + j * 256;
        float v = 0.f;
        if (i < TL) {
            int r = i / 34, c = i - r * 34;
            int gy = y0 - 1 + r, gx = x0 - 1 + c;
            if (gy >= 0 && gy < Hh && gx >= 0 && gx < Ww)
                v = in[gy * Ww + gx];
        }
        pf[j] = v;
    }

    float acc[4][RPT];
#pragma unroll
    for (int o = 0; o < 4; o++)
#pragma unroll
        for (int rr = 0; rr < RPT; rr++) acc[o][rr] = 0.f;

    for (int ci = 0; ci < 64; ci++) {
        const int buf = ci & 1;
#pragma unroll
        for (int j = 0; j < NP; j++) {
            int i = tid + j * 256;
            if (i < TL) {
                int r = i / 34, c = i - r * 34;
                tin[buf][r][c] = pf[j];
            }
        }
        __syncthreads();

        if (ci < 63) {
            const float* p = in + (ci + 1) * HW;
#pragma unroll
            for (int j = 0; j < NP; j++) {
                int i = tid + j * 256;
                float v = 0.f;
                if (i < TL) {
                    int r = i / 34, c = i - r * 34;
                    int gy = y0 - 1 + r, gx = x0 - 1 + c;
                    if (gy >= 0 && gy < Hh && gx >= 0 && gx < Ww)
                        v = p[gy * Ww + gx];
                }
                pf[j] = v;
            }
        }

        float v[RPT][9];
#pragma unroll
        for (int rr = 0; rr < RPT; rr++) {
            int yl = ty + 8 * rr;
#pragma unroll
            for (int dy = 0; dy < 3; dy++)
#pragma unroll
                for (int dx = 0; dx < 3; dx++)
                    v[rr][dy * 3 + dx] = tin[buf][yl + dy][tx + dx];
        }
#pragma unroll
        for (int o = 0; o < 4; o++) {
            float w9[9];
#pragma unroll
            for (int k = 0; k < 9; k++) w9[k] = wsm[ci][o * 9 + k];
#pragma unroll
            for (int rr = 0; rr < RPT; rr++)
#pragma unroll
                for (int k = 0; k < 9; k++)
                    acc[o][rr] = fmaf(v[rr][k], w9[k], acc[o][rr]);
        }
    }

    const int gx = x0 + tx;
#pragma unroll
    for (int o = 0; o < 4; o++) {
        float b = bias[og + o];
#pragma unroll
        for (int rr = 0; rr < RPT; rr++) {
            int gy = y0 + ty + 8 * rr;
            float r = acc[o][rr] + b;
            if (doRelu) r = fmaxf(r, 0.f);
            out[(og + o) * HW + gy * Ww + gx] = r;
        }
    }
}

// ---------------------------------------------------------------------------
// L2-normalized 3x3 patch vectors (fp32, for rescore) + raw 96-dim column
// features (bf16, for the factorized GEMM) + reciprocal patch norms.
// q and k in one launch: blockIdx.y = 0 -> q, 1 -> k. grid (9216,2), blk 288.
// ---------------------------------------------------------------------------
__global__ void patch_norm_kernel(
    const float* __restrict__ fq, const float* __restrict__ fk,
    float* __restrict__ vq, float* __restrict__ vk,
    __nv_bfloat16* __restrict__ colq, __nv_bfloat16* __restrict__ colk,
    float* __restrict__ rnq, float* __restrict__ rnk)
{
    const float* f = blockIdx.y ? fk : fq;
    float* vec = blockIdx.y ? vk : vq;
    __nv_bfloat16* col = blockIdx.y ? colk : colq;
    float* rn = blockIdx.y ? rnk : rnq;

    const int l = blockIdx.x;
    const int y = l / Ww, x = l - y * Ww;
    const int d = threadIdx.x;
    const int c = d / 9, ij = d - c * 9;
    const int dy = ij / 3 - 1, dx = ij % 3 - 1;
    const int yy = y + dy, xx = x + dx;

    float v = 0.f;
    if (yy >= 0 && yy < Hh && xx >= 0 && xx < Ww)
        v = f[c * HW + yy * Ww + xx];

    __shared__ float red[9];
    __shared__ float nrm;
    float s = v * v;
#pragma unroll
    for (int off = 16; off > 0; off >>= 1)
        s += __shfl_down_sync(0xffffffffu, s, off);
    if ((d & 31) == 0) red[d >> 5] = s;
    __syncthreads();
    if (d == 0) {
        float t = 0.f;
#pragma unroll
        for (int i = 0; i < 9; i++) t += red[i];
        nrm = fmaxf(sqrtf(t), 1e-12f);
    }
    __syncthreads();
    vec[l * DQ + d] = v / nrm;
    if (dx == 0)                       // column feature: raw value, dx==0 taps
        col[l * KD + (dy + 1) * 32 + c] = __float2bfloat16(v);
    if (d == 0) rn[l] = 1.f / nrm;
}

// ---------------------------------------------------------------------------
__global__ void transpose_x_kernel(const float* __restrict__ x,
                                   float* __restrict__ xT)
{
    int i = blockIdx.x * 256 + threadIdx.x;
    if (i < CIN * HW) {
        int p = i >> 6, c = i & 63;
        xT[i] = x[c * HW + p];
    }
}

// ---------------------------------------------------------------------------
// Factorized similarity + streaming top-5 + exact fp32 rescore.
// Per CTA: 64 queries; 96 tiles of 96 keys. Per tile: one M=128 N=96 K=96
// bf16 GEMM on column features (16-row/col halos), then masked 3-term
// diagonal sum * rnk gives patch scores. Single barrier/tile; A + scores
// double-buffered, rk triple-buffered; scan overlapped post-barrier.
// grid 144, block 256, dynamic smem 176768 B.
// ---------------------------------------------------------------------------
#define TK     96                       // output keys per tile
#define AROWS  128                      // staged key rows (halo 16 each side)
#define BROWS  96                       // staged query rows (halo 16)
#define ASTRB  208                      // bytes per smem row (96 bf16 + pad)
#define ABUF   (AROWS * ASTRB)          // 26624
#define SM_B   (2 * ABUF)               // 53248
#define SM_SC  (SM_B + BROWS * ASTRB)   // 73216
#define SCSTR  100                      // floats per score row (96 + pad)
#define SCBUF  (AROWS * SCSTR * 4)      // 51200
#define SM_RK  (SM_SC + 2 * SCBUF)      // 175616
#define SIM_SMEM (SM_RK + 3 * TK * 4)   // 176768

struct SimCand { float v[64][32]; int id[64][32]; };

__global__ void __launch_bounds__(256, 1) sim_top5_v4(
    const __nv_bfloat16* __restrict__ colk,
    const __nv_bfloat16* __restrict__ colq,
    const float* __restrict__ Kn,
    const float* __restrict__ Qn,
    const float* __restrict__ rnk,
    float* __restrict__ tvals,
    int*   __restrict__ tidx)
{
    extern __shared__ __align__(16) char dynsm[];
    const uint32_t smb = smem_u32(dynsm);
    float* scoresAll = (float*)(dynsm + SM_SC);
    float* rkt       = (float*)(dynsm + SM_RK);
    SimCand* cand    = (SimCand*)(dynsm + SM_SC);   // aliases score buf 0

    const int tid  = threadIdx.x;
    const int lane = tid & 31;
    const int wid  = tid >> 5;
    const int q0   = blockIdx.x * 64;

    const int wM = (wid & 3) * 32;      // warp key-row offset (M=128, 4 warps)
    const int wN = (wid >> 2) * 48;     // warp query offset  (N=96,  2 warps)

    const int sRow = tid >> 1, sHalf = tid & 1;     // staging roles

    // ---- stage B once (96 query rows: q0-16 .. q0+80, clamped) ----
    if (tid < 192) {
        int gq = q0 - 16 + sRow;
        gq = min(max(gq, 0), LQ - 1);
        const __nv_bfloat16* src = colq + (size_t)gq * KD + sHalf * 48;
        uint32_t dst = smb + SM_B + sRow * ASTRB + sHalf * 96;
#pragma unroll
        for (int j = 0; j < 6; j++) cp16(dst + j * 16, src + j * 8);
    }
    // ---- stage A tile 0 + rk tile 0 ----
    {
        int gk = -16 + sRow;
        gk = min(max(gk, 0), LQ - 1);
        const __nv_bfloat16* src = colk + (size_t)gk * KD + sHalf * 48;
        uint32_t dst = smb + sRow * ASTRB + sHalf * 96;
#pragma unroll
        for (int j = 0; j < 6; j++) cp16(dst + j * 16, src + j * 8);
        if (tid < TK) cp4(smb + SM_RK + tid * 4, rnk + tid);
    }
    CP_COMMIT();
    CP_WAIT0();
    __syncthreads();

    // ldmatrix byte offsets
    const uint32_t aRowByte = (uint32_t)(wM + (lane & 15)) * ASTRB
                            + ((lane >> 4) & 1) * 16;
    const uint32_t bByte = smb + SM_B
        + (uint32_t)(wN + ((lane >> 4) & 1) * 8 + (lane & 7)) * ASTRB
        + ((lane >> 3) & 1) * 16;

    float v8[8]; int i8[8];
#pragma unroll
    for (int r = 0; r < 8; r++) { v8[r] = -1e30f; i8[r] = 0; }
    const int qScan = tid & 63, span = tid >> 6;
    const int qc = qScan + 16;
    const int qx = (q0 + qScan) % Ww;

    for (int kt = 0; kt < 96; kt++) {
        const int buf = kt & 1;

        // prefetch next A tile + rk (triple-buffered rk: scan(kt) still
        // reads rkt[kt%3]; this writes (kt+1)%3)
        if (kt < 95) {
            int base = (kt + 1) * TK - 16;
            int gk = min(max(base + sRow, 0), LQ - 1);
            const __nv_bfloat16* src = colk + (size_t)gk * KD + sHalf * 48;
            uint32_t dst = smb + (buf ^ 1) * ABUF + sRow * ASTRB + sHalf * 96;
#pragma unroll
            for (int j = 0; j < 6; j++) cp16(dst + j * 16, src + j * 8);
            if (tid < TK)
                cp4(smb + SM_RK + (((kt + 1) % 3) * TK + tid) * 4,
                    rnk + (kt + 1) * TK + tid);
            CP_COMMIT();
        }

        // ---- GEMM: M=128 x N=96 x K=96 ----
        float acc[12][4];
#pragma unroll
        for (int f = 0; f < 12; f++)
#pragma unroll
            for (int e = 0; e < 4; e++) acc[f][e] = 0.f;

        const uint32_t aBase = smb + buf * ABUF;
#pragma unroll
        for (int ks = 0; ks < 6; ks++) {
            const uint32_t kb = ks * 32;
            uint32_t a0[4], a1[4], b0[4], b1[4], b2[4];
            ldsm4(a0, aBase + aRowByte + kb);
            ldsm4(a1, aBase + aRowByte + 16 * ASTRB + kb);
            ldsm4(b0, bByte + kb);
            ldsm4(b1, bByte + 16 * ASTRB + kb);
            ldsm4(b2, bByte + 32 * ASTRB + kb);
            mma16816(acc[0], a0, b0);     mma16816(acc[6],  a1, b0);
            mma16816(acc[1], a0, b0 + 2); mma16816(acc[7],  a1, b0 + 2);
            mma16816(acc[2], a0, b1);     mma16816(acc[8],  a1, b1);
            mma16816(acc[3], a0, b1 + 2); mma16816(acc[9],  a1, b1 + 2);
            mma16816(acc[4], a0, b2);     mma16816(acc[10], a1, b2);
            mma16816(acc[5], a0, b2 + 2); mma16816(acc[11], a1, b2 + 2);
        }

        // ---- G1 frags -> scores[key][query] ----
        float* sc = scoresAll + buf * (AROWS * SCSTR);
#pragma unroll
        for (int mi = 0; mi < 2; mi++)
#pragma unroll
            for (int ni = 0; ni < 6; ni++) {
                const float* d = acc[mi * 6 + ni];
                int r = wM + mi * 16 + (lane >> 2);
                int c = wN + ni * 8 + (lane & 3) * 2;
                *(float2*)&sc[r * SCSTR + c] = make_float2(d[0], d[1]);
                *(float2*)&sc[(r + 8) * SCSTR + c] = make_float2(d[2], d[3]);
            }
        if (kt < 95) CP_WAIT0();
        __syncthreads();

        // ---- scan: masked diagonal 3-sum * rnk, streaming top-8 ----
        {
            const float* rk = rkt + (kt % 3) * TK;
            const int gBase = kt * TK;
            const int kx0 = span * 24;
#pragma unroll 4
            for (int i = 0; i < 24; i++) {
                int kx = kx0 + i;
                int kr = 16 + kx;
                float mid = sc[kr * SCSTR + qc];
                float lo  = sc[(kr - 1) * SCSTR + qc - 1];
                float hi  = sc[(kr + 1) * SCSTR + qc + 1];
                bool mn = (kx > 0) && (qx > 0);
                bool mp = (kx < Ww - 1) && (qx < Ww - 1);
                float s = mid + (mn ? lo : 0.f) + (mp ? hi : 0.f);
                s *= rk[kx];
                if (s > v8[7]) {
                    v8[7] = s; i8[7] = gBase + kx;
#pragma unroll
                    for (int r = 7; r > 0; r--)
                        if (v8[r] > v8[r - 1]) {
                            float tv = v8[r - 1]; v8[r - 1] = v8[r]; v8[r] = tv;
                            int ti = i8[r - 1]; i8[r - 1] = i8[r]; i8[r] = ti;
                        }
                }
            }
        }
    }
    __syncthreads();   // all scans done before cand aliases score buf 0

    // ---- candidates -> smem ----
#pragma unroll
    for (int r = 0; r < 8; r++) {
        cand->v [qScan][span * 8 + r] = v8[r];
        cand->id[qScan][span * 8 + r] = i8[r];
    }
    __syncthreads();

    // ---- exact fp32 rescore: 8 candidates per thread ----
    {
        const float4* qr = (const float4*)(Qn + (size_t)(q0 + qScan) * DQ);
        int ids[8];
#pragma unroll
        for (int j = 0; j < 8; j++) ids[j] = cand->id[qScan][span * 8 + j];
#pragma unroll
        for (int j = 0; j < 8; j++) {
            const float4* kr = (const float4*)(Kn + (size_t)ids[j] * DQ);
            float s = 0.f;
#pragma unroll 4
            for (int t = 0; t < 72; t++) {
                float4 a = qr[t], b = kr[t];
                s += a.x * b.x; s += a.y * b.y; s += a.z * b.z; s += a.w * b.w;
            }
            cand->v[qScan][span * 8 + j] = s;
        }
    }
    __syncthreads();

    // ---- final top-5 selection (tie -> lower index) ----
    if (tid < 64) {
        int q = tid;
        for (int r = 0; r < 5; r++) {
            float best = -1e30f; int bi = 0x7fffffff; int bj = 0;
            for (int j = 0; j < 32; j++) {
                float v = cand->v[q][j]; int id = cand->id[q][j];
                if (v > best || (v == best && id < bi)) { best = v; bi = id; bj = j; }
            }
            tvals[(q0 + q) * 5 + r] = best;
            tidx [(q0 + q) * 5 + r] = bi;
            cand->v[q][bj] = -1e31f;
        }
    }
}

// ---------------------------------------------------------------------------
__global__ void assemble_kernel(const float* __restrict__ x,
                                const float* __restrict__ xT,
                                const float* __restrict__ feat,
                                const float* __restrict__ tvals,
                                const int*   __restrict__ tidx,
                                float* __restrict__ out)
{
    const int tid = threadIdx.x;
    const int pix = blockIdx.x * 4 + (tid >> 6);
    const int c = tid & 63;
    const int Y = pix / Ww, X = pix - Y * Ww;

    float s = 0.f;
#pragma unroll
    for (int r = 1; r < 5; r++) {
        float S = tvals[pix * 5 + r];
        float inner = 0.f;
#pragma unroll
        for (int dy = -1; dy <= 1; dy++) {
            int ly = Y + dy;
            if (ly < 0 || ly >= Hh) continue;
#pragma unroll
            for (int dx = -1; dx <= 1; dx++) {
                int lx = X + dx;
                if (lx < 0 || lx >= Ww) continue;
                int m = tidx[(ly * Ww + lx) * 5 + r];
                int my = m / Ww, mx = m - my * Ww;
                int sy = my - dy, sx = mx - dx;
                if (sy >= 0 && sy < Hh && sx >= 0 && sx < Ww)
                    inner += xT[(sy * Ww + sx) * CIN + c];
            }
        }
        s += S * inner;
    }
    out[c * HW + pix] = feat[c * HW + pix] + x[c * HW + pix] + s * (1.0f / 36.0f);
}

// ---------------------------------------------------------------------------
extern "C" void kernel_launch(void* const* d_in, const int* in_sizes, int n_in,
                              void* d_out, int out_size)
{
    (void)in_sizes; (void)n_in; (void)out_size;
    const float* x  = (const float*)d_in[0];
    const float* W1 = (const float*)d_in[1];
    const float* b1 = (const float*)d_in[2];
    const float* W2 = (const float*)d_in[3];
    const float* b2 = (const float*)d_in[4];
    const float* Wq = (const float*)d_in[5];
    const float* bq = (const float*)d_in[6];
    const float* Wk = (const float*)d_in[7];
    const float* bk = (const float*)d_in[8];
    float* out = (float*)d_out;

    float *t1, *feat, *qb, *kb, *Qn, *Kn, *xT, *tv, *rnq, *rnk;
    __nv_bfloat16 *colq, *colk;
    int* ti;
    cudaGetSymbolAddress((void**)&t1,   g_t1);
    cudaGetSymbolAddress((void**)&feat, g_feat);
    cudaGetSymbolAddress((void**)&qb,   g_q);
    cudaGetSymbolAddress((void**)&kb,   g_k);
    cudaGetSymbolAddress((void**)&Qn,   g_Qn);
    cudaGetSymbolAddress((void**)&Kn,   g_Kn);
    cudaGetSymbolAddress((void**)&colq, g_colq);
    cudaGetSymbolAddress((void**)&colk, g_colk);
    cudaGetSymbolAddress((void**)&rnq,  g_rnq);
    cudaGetSymbolAddress((void**)&rnk,  g_rnk);
    cudaGetSymbolAddress((void**)&xT,   g_xT);
    cudaGetSymbolAddress((void**)&tv,   g_tv);
    cudaGetSymbolAddress((void**)&ti,   g_ti);

    cudaFuncSetAttribute(sim_top5_v4,
                         cudaFuncAttributeMaxDynamicSharedMemorySize, SIM_SMEM);

    dim3 cblk(32, 8);
    conv3x3_t<2><<<dim3(3, 6, 16), cblk>>>(x,  W1, b1, t1,   1);
    conv3x3_t<2><<<dim3(3, 6, 16), cblk>>>(t1, W2, b2, feat, 1);
    conv3x3_t<1><<<dim3(3, 12, 8), cblk>>>(x,  Wq, bq, qb,   0);
    conv3x3_t<1><<<dim3(3, 12, 8), cblk>>>(x,  Wk, bk, kb,   0);

    patch_norm_kernel<<<dim3(LQ, 2), DQ>>>(qb, kb, Qn, Kn,
                                           colq, colk, rnq, rnk);
    transpose_x_kernel<<<(CIN * HW + 255) / 256, 256>>>(x, xT);

    sim_top5_v4<<<144, 256, SIM_SMEM>>>(colk, colq, Kn, Qn, rnk, tv, ti);

    assemble_kernel<<<HW / 4, 256>>>(x, xT, feat, tv, ti, out);
}